// round 2
// baseline (speedup 1.0000x reference)
#include <cuda_runtime.h>

#define RES 30
#define NI 32
#define NC 32
#define NPTS (NI * NC)      // 1024 intervals*corners per sample
#define GRID_PTS (RES * RES) // 900

// dist^2 scale: -0.5 / BW^2 = -0.5 / 0.0025 = -200
#define KSCALE (-200.0f)

__global__ __launch_bounds__(128, 1)
void persim_kernel(const float* __restrict__ births,
                   const float* __restrict__ deaths,
                   float* __restrict__ out) {
    const int s   = blockIdx.x;
    const int tid = threadIdx.x;

    __shared__ float4 spts[NPTS];   // {bx, by, dx, dy} per (i,c)
    __shared__ float  axx[RES], axy[RES];
    __shared__ float  w2s[NI];
    __shared__ float  red[16];      // 4 warps * {mnx,mxx,mny,mxy}
    __shared__ float  slo[2], shi[2];

    const float2* bp = (const float2*)(births + (size_t)s * NPTS * 2);
    const float2* dp = (const float2*)(deaths + (size_t)s * NPTS * 2);

    // ---- Phase 1: stage points to smem + per-sample bbox reduction ----
    float mnx = 1e30f, mxx = -1e30f, mny = 1e30f, mxy = -1e30f;
    for (int p = tid; p < NPTS; p += 128) {
        float2 b = bp[p];
        float2 d = dp[p];
        spts[p] = make_float4(b.x, b.y, d.x, d.y);
        mnx = fminf(mnx, fminf(b.x, d.x));
        mxx = fmaxf(mxx, fmaxf(b.x, d.x));
        mny = fminf(mny, fminf(b.y, d.y));
        mxy = fmaxf(mxy, fmaxf(b.y, d.y));
    }
#pragma unroll
    for (int o = 16; o; o >>= 1) {
        mnx = fminf(mnx, __shfl_xor_sync(0xffffffffu, mnx, o));
        mxx = fmaxf(mxx, __shfl_xor_sync(0xffffffffu, mxx, o));
        mny = fminf(mny, __shfl_xor_sync(0xffffffffu, mny, o));
        mxy = fmaxf(mxy, __shfl_xor_sync(0xffffffffu, mxy, o));
    }
    const int wid  = tid >> 5;
    const int lane = tid & 31;
    if (lane == 0) {
        red[wid * 4 + 0] = mnx;
        red[wid * 4 + 1] = mxx;
        red[wid * 4 + 2] = mny;
        red[wid * 4 + 3] = mxy;
    }
    __syncthreads();

    if (tid == 0) {
        float a = red[0], b = red[1], c = red[2], d = red[3];
#pragma unroll
        for (int w = 1; w < 4; w++) {
            a = fminf(a, red[w * 4 + 0]);
            b = fmaxf(b, red[w * 4 + 1]);
            c = fminf(c, red[w * 4 + 2]);
            d = fmaxf(d, red[w * 4 + 3]);
        }
        float mgx = 0.1f * (b - a);
        float mgy = 0.1f * (d - c);
        slo[0] = a - mgx; shi[0] = b + mgx;
        slo[1] = c - mgy; shi[1] = d + mgy;
    }
    // interval weights w^2 (independent of bbox) in parallel with the final reduce
    if (tid >= 32 && tid < 64) {
        int i = tid - 32;
        float sum = 0.0f;
#pragma unroll 8
        for (int c = 0; c < NC; c++) {
            float4 p = spts[i * NC + c];
            sum += fmaxf(fabsf(p.z - p.x), fabsf(p.w - p.y));
        }
        float w = sum * (1.0f / NC);
        w2s[i] = w * w;
    }
    __syncthreads();

    if (tid < RES) {
        float t = (float)tid * (1.0f / (RES - 1));
        axx[tid] = slo[0] + t * (shi[0] - slo[0]);
        axy[tid] = slo[1] + t * (shi[1] - slo[1]);
    }
    __syncthreads();

    // ---- Phase 2: KDE image. 120 active threads = 30 iy columns x 4 ix-chunks.
    // dy^2 hoisted across the thread's 7-8 ix points (same gy).
    if (tid < 120) {
        const int iy    = tid >> 2;
        const int chunk = tid & 3;
        const int npts  = (chunk < 2) ? 8 : 7;   // ix = chunk + 4k < 30
        const float gy  = axy[iy];

        float gxv[8];
#pragma unroll
        for (int k = 0; k < 8; k++) {
            int ix = chunk + 4 * k;
            gxv[k] = (ix < RES) ? axx[ix] : 0.0f;
        }

        float acc[8];
#pragma unroll
        for (int k = 0; k < 8; k++) acc[k] = 0.0f;

        for (int i = 0; i < NI; i++) {
            float minb[8], mind[8];
#pragma unroll
            for (int k = 0; k < 8; k++) { minb[k] = 1e30f; mind[k] = 1e30f; }

#pragma unroll 4
            for (int c = 0; c < NC; c++) {
                float4 p = spts[i * NC + c];
                float tb = gy - p.y;
                float b2 = tb * tb;          // (gy - by)^2 shared across ix
                float td = gy - p.w;
                float d2 = td * td;          // (gy - dy)^2 shared across ix
#pragma unroll
                for (int k = 0; k < 8; k++) {
                    float dxb = gxv[k] - p.x;
                    minb[k] = fminf(minb[k], fmaf(dxb, dxb, b2));
                    float dxd = gxv[k] - p.z;
                    mind[k] = fminf(mind[k], fmaf(dxd, dxd, d2));
                }
            }

            float wv = w2s[i];
#pragma unroll
            for (int k = 0; k < 8; k++) {
                float m = fmaxf(minb[k], mind[k]);
                acc[k] = fmaf(wv, __expf(KSCALE * m), acc[k]);
            }
        }

        float* orow = out + (size_t)s * GRID_PTS;
#pragma unroll
        for (int k = 0; k < 8; k++) {
            if (k < npts) {
                int ix = chunk + 4 * k;
                orow[ix * RES + iy] = acc[k];
            }
        }
    }
}

extern "C" void kernel_launch(void* const* d_in, const int* in_sizes, int n_in,
                              void* d_out, int out_size) {
    const float* births = (const float*)d_in[0];
    const float* deaths = (const float*)d_in[1];
    float* out = (float*)d_out;
    int S = in_sizes[0] / (NPTS * 2);   // 128 for the reference shapes
    persim_kernel<<<S, 128>>>(births, deaths, out);
}

// round 6
// speedup vs baseline: 1.5058x; 1.5058x over previous
#include <cuda_runtime.h>

#define RES 30
#define NI 32
#define NC 32
#define NPTS (NI * NC)       // 1024
#define GRID_PTS (RES * RES) // 900

// exp(-200*m) == exp2(KS2*m),  KS2 = -200 * log2(e)
#define KS2 (-288.53900817779268f)

typedef unsigned long long ull;

__device__ __forceinline__ ull pk2(float lo, float hi) {
    ull r; asm("mov.b64 %0, {%1, %2};" : "=l"(r) : "f"(lo), "f"(hi)); return r;
}
__device__ __forceinline__ float2 unpk(ull v) {
    float2 r; asm("mov.b64 {%0, %1}, %2;" : "=f"(r.x), "=f"(r.y) : "l"(v)); return r;
}
__device__ __forceinline__ ull addx2(ull a, ull b) {
    ull r; asm("add.rn.f32x2 %0, %1, %2;" : "=l"(r) : "l"(a), "l"(b)); return r;
}
__device__ __forceinline__ ull mulx2(ull a, ull b) {
    ull r; asm("mul.rn.f32x2 %0, %1, %2;" : "=l"(r) : "l"(a), "l"(b)); return r;
}
__device__ __forceinline__ ull fmax2p(ull a, ull b, ull c) {
    ull r; asm("fma.rn.f32x2 %0, %1, %2, %3;" : "=l"(r) : "l"(a), "l"(b), "l"(c)); return r;
}
__device__ __forceinline__ float ex2f(float x) {
    float r; asm("ex2.approx.ftz.f32 %0, %1;" : "=f"(r) : "f"(x)); return r;
}

__global__ __launch_bounds__(256, 1)
void persim_kernel(const float* __restrict__ births,
                   const float* __restrict__ deaths,
                   float* __restrict__ out) {
    const int s   = blockIdx.x;
    const int tid = threadIdx.x;

    __shared__ float4 spts[NPTS];    // {bx, dx, by, dy} per (i,c)
    __shared__ float  axx[RES], axy[RES];
    __shared__ float  w2s[NI];
    __shared__ float  red[32];       // 8 warps * {mnx,mxx,mny,mxy}
    __shared__ float  slo[2], shi[2];
    __shared__ float  pacc[8][128];  // partial acc from upper half, [k][t]

    const float2* bp = (const float2*)(births + (size_t)s * NPTS * 2);
    const float2* dp = (const float2*)(deaths + (size_t)s * NPTS * 2);

    // ---- Phase 1: stage points (birth/death interleaved per coord) + bbox ----
    float mnx = 1e30f, mxx = -1e30f, mny = 1e30f, mxy = -1e30f;
    for (int p = tid; p < NPTS; p += 256) {
        float2 b = bp[p];
        float2 d = dp[p];
        spts[p] = make_float4(b.x, d.x, b.y, d.y);
        mnx = fminf(mnx, fminf(b.x, d.x));
        mxx = fmaxf(mxx, fmaxf(b.x, d.x));
        mny = fminf(mny, fminf(b.y, d.y));
        mxy = fmaxf(mxy, fmaxf(b.y, d.y));
    }
#pragma unroll
    for (int o = 16; o; o >>= 1) {
        mnx = fminf(mnx, __shfl_xor_sync(0xffffffffu, mnx, o));
        mxx = fmaxf(mxx, __shfl_xor_sync(0xffffffffu, mxx, o));
        mny = fminf(mny, __shfl_xor_sync(0xffffffffu, mny, o));
        mxy = fmaxf(mxy, __shfl_xor_sync(0xffffffffu, mxy, o));
    }
    const int wid  = tid >> 5;
    const int lane = tid & 31;
    if (lane == 0) {
        red[wid * 4 + 0] = mnx;
        red[wid * 4 + 1] = mxx;
        red[wid * 4 + 2] = mny;
        red[wid * 4 + 3] = mxy;
    }
    __syncthreads();

    if (tid == 0) {
        float a = red[0], b = red[1], c = red[2], d = red[3];
#pragma unroll
        for (int w = 1; w < 8; w++) {
            a = fminf(a, red[w * 4 + 0]);
            b = fmaxf(b, red[w * 4 + 1]);
            c = fminf(c, red[w * 4 + 2]);
            d = fmaxf(d, red[w * 4 + 3]);
        }
        float mgx = 0.1f * (b - a);
        float mgy = 0.1f * (d - c);
        slo[0] = a - mgx; shi[0] = b + mgx;
        slo[1] = c - mgy; shi[1] = d + mgy;
    }
    // interval weights (warp 1), overlapped with the bbox finalize
    if (tid >= 32 && tid < 64) {
        int i = tid - 32;
        float sum = 0.0f;
#pragma unroll 8
        for (int c = 0; c < NC; c++) {
            float4 p = spts[i * NC + c];                     // {bx,dx,by,dy}
            sum += fmaxf(fabsf(p.y - p.x), fabsf(p.w - p.z));
        }
        float w = sum * (1.0f / NC);
        w2s[i] = w * w;
    }
    __syncthreads();

    if (tid < RES) {
        float t = (float)tid * (1.0f / (RES - 1));
        axx[tid] = slo[0] + t * (shi[0] - slo[0]);
        axy[tid] = slo[1] + t * (shi[1] - slo[1]);
    }
    __syncthreads();

    // ---- Phase 2: KDE. Two independent warp-sets split the interval loop:
    //   half 0 (warps 0-3): i = 0..15, half 1 (warps 4-7): i = 16..31.
    // Within each: 120 threads = 30 iy columns x 4 ix-chunks, 7-8 ix each.
    const int half = tid >> 7;
    const int t    = tid & 127;

    float acc[8];
#pragma unroll
    for (int k = 0; k < 8; k++) acc[k] = 0.0f;

    int iy = 0, chunk = 0;
    if (t < 120) {
        iy    = t >> 2;
        chunk = t & 3;
        const float gy = axy[iy];
        const ull  ngy = pk2(-gy, -gy);

        ull ngx[8];
#pragma unroll
        for (int k = 0; k < 8; k++) {
            int ix = chunk + 4 * k;
            float gx = (ix < RES) ? axx[ix] : 0.0f;
            ngx[k] = pk2(-gx, -gx);
        }

        const float4* pp = spts + half * (16 * NC);
        const int i0 = half * 16;

        for (int i = 0; i < 16; i++) {
            float minb[8], mind[8];
#pragma unroll
            for (int k = 0; k < 8; k++) { minb[k] = 1e30f; mind[k] = 1e30f; }

#pragma unroll 4
            for (int c = 0; c < NC; c++) {
                float4 p = pp[i * NC + c];           // {bx, dx, by, dy}
                ull xpair = pk2(p.x, p.y);           // (bx, dx)  — aligned pair, no movs
                ull ypair = pk2(p.z, p.w);           // (by, dy)
                ull ty = addx2(ypair, ngy);          // (by-gy, dy-gy)
                ull y2 = mulx2(ty, ty);              // (b_y2, d_y2)
#pragma unroll
                for (int k = 0; k < 8; k++) {
                    ull tx = addx2(xpair, ngx[k]);   // (bx-gx, dx-gx)
                    ull m  = fmax2p(tx, tx, y2);     // (db2, dd2)
                    float2 mf = unpk(m);
                    minb[k] = fminf(minb[k], mf.x);
                    mind[k] = fminf(mind[k], mf.y);
                }
            }

            float wv = w2s[i0 + i];
#pragma unroll
            for (int k = 0; k < 8; k++) {
                float mm = fmaxf(minb[k], mind[k]);
                acc[k] = fmaf(wv, ex2f(KS2 * mm), acc[k]);
            }
        }
    }

    // upper half publishes partials
    if (half == 1 && t < 120) {
#pragma unroll
        for (int k = 0; k < 8; k++) pacc[k][t] = acc[k];
    }
    __syncthreads();

    if (half == 0 && t < 120) {
        const int npts = (chunk < 2) ? 8 : 7;
        float* orow = out + (size_t)s * GRID_PTS;
#pragma unroll
        for (int k = 0; k < 8; k++) {
            if (k < npts) {
                int ix = chunk + 4 * k;
                orow[ix * RES + iy] = acc[k] + pacc[k][t];
            }
        }
    }
}

extern "C" void kernel_launch(void* const* d_in, const int* in_sizes, int n_in,
                              void* d_out, int out_size) {
    const float* births = (const float*)d_in[0];
    const float* deaths = (const float*)d_in[1];
    float* out = (float*)d_out;
    int S = in_sizes[0] / (NPTS * 2);   // 128 for the reference shapes
    persim_kernel<<<S, 256>>>(births, deaths, out);
}

// round 7
// speedup vs baseline: 1.7381x; 1.1543x over previous
#include <cuda_runtime.h>

#define RES 30
#define NI 32
#define NC 32
#define NPTS (NI * NC)       // 1024
#define GRID_PTS (RES * RES) // 900

// exp(-200*m) == exp2(KS2*m),  KS2 = -200 * log2(e)
#define KS2 (-288.53900817779268f)

typedef unsigned long long ull;

__device__ __forceinline__ ull pk2(float lo, float hi) {
    ull r; asm("mov.b64 %0, {%1, %2};" : "=l"(r) : "f"(lo), "f"(hi)); return r;
}
__device__ __forceinline__ float2 unpk(ull v) {
    float2 r; asm("mov.b64 {%0, %1}, %2;" : "=f"(r.x), "=f"(r.y) : "l"(v)); return r;
}
__device__ __forceinline__ ull fma2(ull a, ull b, ull c) {
    ull r; asm("fma.rn.f32x2 %0, %1, %2, %3;" : "=l"(r) : "l"(a), "l"(b), "l"(c)); return r;
}
__device__ __forceinline__ float ex2f(float x) {
    float r; asm("ex2.approx.ftz.f32 %0, %1;" : "=f"(r) : "f"(x)); return r;
}

__global__ __launch_bounds__(512, 1)
void persim_kernel(const float* __restrict__ births,
                   const float* __restrict__ deaths,
                   float* __restrict__ out) {
    const int s   = blockIdx.x;
    const int tid = threadIdx.x;

    __shared__ float4 xr[NPTS];      // {bx, dx, rb, rd} per (i,c), r = px^2+py^2
    __shared__ float2 yv[NPTS];      // {by, dy}
    __shared__ float  axx[RES], axy[RES];
    __shared__ float  w2s[NI];
    __shared__ float  red[64];       // 16 warps * {mnx,mxx,mny,mxy}
    __shared__ float  slo[2], shi[2];
    __shared__ float  pacc[3][8][128]; // partials from quarters 1..3

    const float2* bp = (const float2*)(births + (size_t)s * NPTS * 2);
    const float2* dp = (const float2*)(deaths + (size_t)s * NPTS * 2);

    // ---- Phase 1: stage points + per-corner r, bbox reduction ----
    float mnx = 1e30f, mxx = -1e30f, mny = 1e30f, mxy = -1e30f;
    for (int p = tid; p < NPTS; p += 512) {
        float2 b = bp[p];
        float2 d = dp[p];
        float rb = fmaf(b.x, b.x, b.y * b.y);
        float rd = fmaf(d.x, d.x, d.y * d.y);
        xr[p] = make_float4(b.x, d.x, rb, rd);
        yv[p] = make_float2(b.y, d.y);
        mnx = fminf(mnx, fminf(b.x, d.x));
        mxx = fmaxf(mxx, fmaxf(b.x, d.x));
        mny = fminf(mny, fminf(b.y, d.y));
        mxy = fmaxf(mxy, fmaxf(b.y, d.y));
    }
#pragma unroll
    for (int o = 16; o; o >>= 1) {
        mnx = fminf(mnx, __shfl_xor_sync(0xffffffffu, mnx, o));
        mxx = fmaxf(mxx, __shfl_xor_sync(0xffffffffu, mxx, o));
        mny = fminf(mny, __shfl_xor_sync(0xffffffffu, mny, o));
        mxy = fmaxf(mxy, __shfl_xor_sync(0xffffffffu, mxy, o));
    }
    const int wid  = tid >> 5;
    const int lane = tid & 31;
    if (lane == 0) {
        red[wid * 4 + 0] = mnx;
        red[wid * 4 + 1] = mxx;
        red[wid * 4 + 2] = mny;
        red[wid * 4 + 3] = mxy;
    }
    __syncthreads();

    if (tid == 0) {
        float a = red[0], b = red[1], c = red[2], d = red[3];
#pragma unroll
        for (int w = 1; w < 16; w++) {
            a = fminf(a, red[w * 4 + 0]);
            b = fmaxf(b, red[w * 4 + 1]);
            c = fminf(c, red[w * 4 + 2]);
            d = fmaxf(d, red[w * 4 + 3]);
        }
        float mgx = 0.1f * (b - a);
        float mgy = 0.1f * (d - c);
        slo[0] = a - mgx; shi[0] = b + mgx;
        slo[1] = c - mgy; shi[1] = d + mgy;
    }
    // interval weights (warp 1), overlapped with bbox finalize
    if (tid >= 32 && tid < 64) {
        int i = tid - 32;
        float sum = 0.0f;
#pragma unroll 8
        for (int c = 0; c < NC; c++) {
            float4 P = xr[i * NC + c];
            float2 Y = yv[i * NC + c];
            sum += fmaxf(fabsf(P.y - P.x), fabsf(Y.y - Y.x));
        }
        float w = sum * (1.0f / NC);
        w2s[i] = w * w;
    }
    __syncthreads();

    if (tid < RES) {
        float t = (float)tid * (1.0f / (RES - 1));
        axx[tid] = slo[0] + t * (shi[0] - slo[0]);
        axy[tid] = slo[1] + t * (shi[1] - slo[1]);
    }
    __syncthreads();

    // ---- Phase 2: KDE. 4 warp-sets (quarters) split the interval loop:
    // quarter q handles i = q*8 .. q*8+7. Within each: 120 threads =
    // 30 iy columns x 4 ix-chunks, 7-8 ix points per thread.
    //
    // dist^2 = gx^2+gy^2 + (r - 2*gx*px - 2*gy*py);  min over corners of
    // the bracket (g-terms constant), gx^2+gy^2 folded into the exp arg.
    const int quarter = tid >> 7;
    const int t       = tid & 127;

    float acc[8];
#pragma unroll
    for (int k = 0; k < 8; k++) acc[k] = 0.0f;

    int iy = 0, chunk = 0;
    if (t < 120) {
        iy    = t >> 2;
        chunk = t & 3;
        const float gy  = axy[iy];
        const ull n2gy  = pk2(-2.0f * gy, -2.0f * gy);

        ull   n2gx[8];
        float ks2g2[8];
#pragma unroll
        for (int k = 0; k < 8; k++) {
            int ix = chunk + 4 * k;
            float gx = (ix < RES) ? axx[ix] : 0.0f;
            n2gx[k]  = pk2(-2.0f * gx, -2.0f * gx);
            ks2g2[k] = KS2 * fmaf(gx, gx, gy * gy);
        }

        const int i0 = quarter * 8;
        const float4* xp = xr + i0 * NC;
        const float2* yp = yv + i0 * NC;

        for (int i = 0; i < 8; i++) {
            float minb[8], mind[8];
#pragma unroll
            for (int k = 0; k < 8; k++) { minb[k] = 1e30f; mind[k] = 1e30f; }

#pragma unroll 4
            for (int c = 0; c < NC; c++) {
                float4 P = xp[i * NC + c];          // {bx, dx, rb, rd}
                float2 Y = yp[i * NC + c];          // {by, dy}
                ull xpair = pk2(P.x, P.y);
                ull rpair = pk2(P.z, P.w);
                ull ypair = pk2(Y.x, Y.y);
                ull tpair = fma2(ypair, n2gy, rpair);   // r - 2gy*py
#pragma unroll
                for (int k = 0; k < 8; k++) {
                    ull m = fma2(xpair, n2gx[k], tpair); // r - 2g.p
                    float2 mf = unpk(m);
                    minb[k] = fminf(minb[k], mf.x);
                    mind[k] = fminf(mind[k], mf.y);
                }
            }

            float wv = w2s[i0 + i];
#pragma unroll
            for (int k = 0; k < 8; k++) {
                float mm  = fmaxf(minb[k], mind[k]);
                float arg = fmaf(KS2, mm, ks2g2[k]);   // KS2*(g2 + m)
                acc[k] = fmaf(wv, ex2f(arg), acc[k]);
            }
        }
    }

    // quarters 1-3 publish partials
    if (quarter != 0 && t < 120) {
#pragma unroll
        for (int k = 0; k < 8; k++) pacc[quarter - 1][k][t] = acc[k];
    }
    __syncthreads();

    if (quarter == 0 && t < 120) {
        const int npts = (chunk < 2) ? 8 : 7;
        float* orow = out + (size_t)s * GRID_PTS;
#pragma unroll
        for (int k = 0; k < 8; k++) {
            if (k < npts) {
                int ix = chunk + 4 * k;
                float v = acc[k] + pacc[0][k][t] + pacc[1][k][t] + pacc[2][k][t];
                orow[ix * RES + iy] = v;
            }
        }
    }
}

extern "C" void kernel_launch(void* const* d_in, const int* in_sizes, int n_in,
                              void* d_out, int out_size) {
    const float* births = (const float*)d_in[0];
    const float* deaths = (const float*)d_in[1];
    float* out = (float*)d_out;
    int S = in_sizes[0] / (NPTS * 2);   // 128 for the reference shapes
    persim_kernel<<<S, 512>>>(births, deaths, out);
}